// round 1
// baseline (speedup 1.0000x reference)
#include <cuda_runtime.h>
#include <math.h>

// Problem constants
#define Nn 16            // B*T
#define Cc 512
#define Ss 1024          // H*W
#define NHEADS 8
#define HD 64
#define D3 1536          // 3*C
#define CPG 16           // channels per group (C/32)

// Scratch (device globals; no cudaMalloc allowed)
__device__ float g_hn [Nn * Cc * Ss];          // groupnorm output [n][c][s]
__device__ float g_q  [Nn * NHEADS * Ss * HD]; // [nh][s][e]
__device__ float g_k  [Nn * NHEADS * Ss * HD];
__device__ float g_v  [Nn * NHEADS * Ss * HD];
__device__ float g_att[Nn * Cc * Ss];          // attention out [n][c][s], c = head*64+e

// ---------------------------------------------------------------------------
// Kernel 1: GroupNorm (32 groups, eps=1e-6, affine)
// one block per (n, group); reduce 16*1024 = 16384 elements
// ---------------------------------------------------------------------------
__global__ void __launch_bounds__(256) gn_kernel(const float* __restrict__ x,
                                                 const float* __restrict__ sc,
                                                 const float* __restrict__ bi)
{
    int n = blockIdx.x >> 5;
    int g = blockIdx.x & 31;
    const float* px = x   + (size_t)(n * Cc + g * CPG) * Ss;
    float*       ph = g_hn + (size_t)(n * Cc + g * CPG) * Ss;
    const int M = CPG * Ss;  // 16384

    float s = 0.f, ss = 0.f;
    for (int i = threadIdx.x * 4; i < M; i += 256 * 4) {
        float4 v = *(const float4*)&px[i];
        s  += v.x + v.y + v.z + v.w;
        ss += v.x*v.x + v.y*v.y + v.z*v.z + v.w*v.w;
    }
#pragma unroll
    for (int o = 16; o; o >>= 1) {
        s  += __shfl_xor_sync(0xffffffffu, s,  o);
        ss += __shfl_xor_sync(0xffffffffu, ss, o);
    }
    __shared__ float r0[8], r1[8];
    __shared__ float s_mean, s_inv;
    if ((threadIdx.x & 31) == 0) { r0[threadIdx.x >> 5] = s; r1[threadIdx.x >> 5] = ss; }
    __syncthreads();
    if (threadIdx.x == 0) {
        float a = 0.f, b2 = 0.f;
#pragma unroll
        for (int i = 0; i < 8; i++) { a += r0[i]; b2 += r1[i]; }
        float mean = a / (float)M;
        float var  = b2 / (float)M - mean * mean;
        s_mean = mean;
        s_inv  = rsqrtf(var + 1e-6f);
    }
    __syncthreads();
    float mean = s_mean, inv = s_inv;
    for (int i = threadIdx.x * 4; i < M; i += 256 * 4) {
        int c = g * CPG + (i >> 10);            // 4 consecutive elems share channel
        float scv = sc[c] * inv;
        float biv = bi[c] - mean * scv;
        float4 v = *(const float4*)&px[i];
        float4 o;
        o.x = v.x * scv + biv;
        o.y = v.y * scv + biv;
        o.z = v.z * scv + biv;
        o.w = v.w * scv + biv;
        *(float4*)&ph[i] = o;
    }
}

// ---------------------------------------------------------------------------
// Kernel 2: QKV projection GEMM per n:
//   out[s][d] = sum_c hn[n][c][s] * w_qkv[c][d] + b_qkv[d]
// 64x64 tiles, BK=16, 256 threads, 4x4 microtile. Epilogue scatters into
// g_q/g_k/g_v with layout [(n*8+head)][s][e] (e contiguous -> float4 stores).
// ---------------------------------------------------------------------------
__global__ void __launch_bounds__(256) qkv_kernel(const float* __restrict__ w,
                                                  const float* __restrict__ bq)
{
    __shared__ float As[16 * 68];   // [k][s_local]
    __shared__ float Bs[16 * 68];   // [k][d_local]
    int n  = blockIdx.z;
    int s0 = blockIdx.x * 64;
    int d0 = blockIdx.y * 64;
    int tid = threadIdx.x, tx = tid & 15, ty = tid >> 4;
    int lr = tid >> 4;              // load row  0..15
    int lc = (tid & 15) * 4;        // load col  0..60

    const float* A = g_hn + (size_t)n * Cc * Ss;
    float acc[4][4] = {};

    for (int c0 = 0; c0 < Cc; c0 += 16) {
        *(float4*)&As[lr * 68 + lc] = *(const float4*)&A[(size_t)(c0 + lr) * Ss + s0 + lc];
        *(float4*)&Bs[lr * 68 + lc] = *(const float4*)&w[(size_t)(c0 + lr) * D3 + d0 + lc];
        __syncthreads();
#pragma unroll
        for (int k = 0; k < 16; k++) {
            float4 a4 = *(float4*)&As[k * 68 + ty * 4];
            float4 b4 = *(float4*)&Bs[k * 68 + tx * 4];
            float av[4] = {a4.x, a4.y, a4.z, a4.w};
            float bv[4] = {b4.x, b4.y, b4.z, b4.w};
#pragma unroll
            for (int i = 0; i < 4; i++)
#pragma unroll
                for (int j = 0; j < 4; j++) acc[i][j] += av[i] * bv[j];
        }
        __syncthreads();
    }

    // d0 is a multiple of 64 so the whole tile lies in one (head, part, e) block
    int head = d0 / 192;
    int part = (d0 % 192) / 64;
    float* dst = (part == 0 ? g_q : (part == 1 ? g_k : g_v))
                 + (size_t)(n * NHEADS + head) * Ss * HD;
    float4 bv = *(const float4*)&bq[d0 + tx * 4];
#pragma unroll
    for (int i = 0; i < 4; i++) {
        int s = s0 + ty * 4 + i;
        float4 o = make_float4(acc[i][0] + bv.x, acc[i][1] + bv.y,
                               acc[i][2] + bv.z, acc[i][3] + bv.w);
        *(float4*)&dst[(size_t)s * HD + tx * 4] = o;
    }
}

// ---------------------------------------------------------------------------
// Kernel 3: flash attention. One block per (nh, q-tile of 64).
// Two 64x64x64 register-tiled GEMMs with online softmax. K smem buffer is
// reused for P (K no longer needed once S is computed).
// Dynamic smem = 3 * 64 * 68 * 4 = 52224 bytes.
// ---------------------------------------------------------------------------
__global__ void __launch_bounds__(256) attn_kernel()
{
    extern __shared__ float sm[];
    float* Qs = sm;                 // [e][q] stride 68 (Q transposed, pre-scaled)
    float* Ks = sm + 64 * 68;       // [e][j] stride 68; later reused as P [j][q]
    float* Vs = sm + 2 * 64 * 68;   // [j][e] stride 68

    int nh = blockIdx.y;
    int q0 = blockIdx.x * 64;
    const float* Q = g_q + (size_t)nh * Ss * HD;
    const float* K = g_k + (size_t)nh * Ss * HD;
    const float* V = g_v + (size_t)nh * Ss * HD;
    int tid = threadIdx.x, tx = tid & 15, ty = tid >> 4;

    // load Q tile transposed, scaled by 1/sqrt(HD)
#pragma unroll
    for (int it = 0; it < 16; it++) {
        int idx = tid + it * 256;
        int ql = idx >> 6, e = idx & 63;
        Qs[e * 68 + ql] = Q[(size_t)(q0 + ql) * HD + e] * 0.125f;
    }

    float m[4], l[4], o[4][4];
#pragma unroll
    for (int i = 0; i < 4; i++) {
        m[i] = -1e30f; l[i] = 0.f;
#pragma unroll
        for (int j = 0; j < 4; j++) o[i][j] = 0.f;
    }

    for (int kt = 0; kt < 16; kt++) {
        __syncthreads();   // previous iteration done with Ks(P)/Vs; also guards Qs at kt=0
#pragma unroll
        for (int it = 0; it < 16; it++) {
            int idx = tid + it * 256;
            int jl = idx >> 6, e = idx & 63;
            Ks[e * 68 + jl] = K[(size_t)(kt * 64 + jl) * HD + e];
            Vs[jl * 68 + e] = V[(size_t)(kt * 64 + jl) * HD + e];
        }
        __syncthreads();

        // GEMM1: S = Q @ K^T   (s4[i][j], i = q-row, j = key)
        float s4[4][4] = {};
#pragma unroll 8
        for (int e = 0; e < 64; e++) {
            float4 a4 = *(float4*)&Qs[e * 68 + ty * 4];
            float4 b4 = *(float4*)&Ks[e * 68 + tx * 4];
            float av[4] = {a4.x, a4.y, a4.z, a4.w};
            float bv[4] = {b4.x, b4.y, b4.z, b4.w};
#pragma unroll
            for (int i = 0; i < 4; i++)
#pragma unroll
                for (int j = 0; j < 4; j++) s4[i][j] += av[i] * bv[j];
        }

        // online softmax (row = 16 lanes sharing ty; xor-shuffle widths 8..1)
#pragma unroll
        for (int i = 0; i < 4; i++) {
            float mx = fmaxf(fmaxf(s4[i][0], s4[i][1]), fmaxf(s4[i][2], s4[i][3]));
#pragma unroll
            for (int msk = 8; msk; msk >>= 1)
                mx = fmaxf(mx, __shfl_xor_sync(0xffffffffu, mx, msk));
            float mn = fmaxf(m[i], mx);
            float corr = __expf(m[i] - mn);
            float rs = 0.f;
#pragma unroll
            for (int j = 0; j < 4; j++) {
                float p = __expf(s4[i][j] - mn);
                s4[i][j] = p;
                rs += p;
            }
#pragma unroll
            for (int msk = 8; msk; msk >>= 1)
                rs += __shfl_xor_sync(0xffffffffu, rs, msk);
            l[i] = l[i] * corr + rs;
            m[i] = mn;
#pragma unroll
            for (int j = 0; j < 4; j++) o[i][j] *= corr;
        }

        __syncthreads();   // everyone done reading Ks
        // write P transposed into the K buffer: P[j][q]
#pragma unroll
        for (int jj = 0; jj < 4; jj++) {
            *(float4*)&Ks[(tx * 4 + jj) * 68 + ty * 4] =
                make_float4(s4[0][jj], s4[1][jj], s4[2][jj], s4[3][jj]);
        }
        __syncthreads();

        // GEMM2: O += P @ V
#pragma unroll 8
        for (int j = 0; j < 64; j++) {
            float4 a4 = *(float4*)&Ks[j * 68 + ty * 4];   // P[j][q rows]
            float4 b4 = *(float4*)&Vs[j * 68 + tx * 4];   // V[j][e cols]
            float av[4] = {a4.x, a4.y, a4.z, a4.w};
            float bv[4] = {b4.x, b4.y, b4.z, b4.w};
#pragma unroll
            for (int i = 0; i < 4; i++)
#pragma unroll
                for (int jj = 0; jj < 4; jj++) o[i][jj] += av[i] * bv[jj];
        }
    }

    // epilogue: normalize and write to g_att[n][head*64+e][s]
    int n = nh >> 3, head = nh & 7;
#pragma unroll
    for (int i = 0; i < 4; i++) {
        float inv = 1.f / l[i];
        int srow = q0 + ty * 4 + i;
#pragma unroll
        for (int j = 0; j < 4; j++) {
            int e = tx * 4 + j;
            g_att[(size_t)(n * Cc + head * HD + e) * Ss + srow] = o[i][j] * inv;
        }
    }
}

// ---------------------------------------------------------------------------
// Kernel 4: output projection + bias + residual:
//   out[n][c2][s] = x[n][c2][s] + b_out[c2] + sum_c g_att[n][c][s] * w_out[c][c2]
// ---------------------------------------------------------------------------
__global__ void __launch_bounds__(256) oproj_kernel(const float* __restrict__ w,
                                                    const float* __restrict__ bo,
                                                    const float* __restrict__ x,
                                                    float* __restrict__ out)
{
    __shared__ float As[16 * 68];   // [k][c2_local]
    __shared__ float Bs[16 * 68];   // [k][s_local]
    int n   = blockIdx.z;
    int s0  = blockIdx.x * 64;
    int c20 = blockIdx.y * 64;
    int tid = threadIdx.x, tx = tid & 15, ty = tid >> 4;
    int lr = tid >> 4;
    int lc = (tid & 15) * 4;

    const float* Bmat = g_att + (size_t)n * Cc * Ss;
    float acc[4][4] = {};

    for (int c0 = 0; c0 < Cc; c0 += 16) {
        *(float4*)&As[lr * 68 + lc] = *(const float4*)&w[(size_t)(c0 + lr) * Cc + c20 + lc];
        *(float4*)&Bs[lr * 68 + lc] = *(const float4*)&Bmat[(size_t)(c0 + lr) * Ss + s0 + lc];
        __syncthreads();
#pragma unroll
        for (int k = 0; k < 16; k++) {
            float4 a4 = *(float4*)&As[k * 68 + ty * 4];   // c2 dim
            float4 b4 = *(float4*)&Bs[k * 68 + tx * 4];   // s dim
            float av[4] = {a4.x, a4.y, a4.z, a4.w};
            float bv[4] = {b4.x, b4.y, b4.z, b4.w};
#pragma unroll
            for (int i = 0; i < 4; i++)
#pragma unroll
                for (int j = 0; j < 4; j++) acc[i][j] += av[i] * bv[j];
        }
        __syncthreads();
    }

#pragma unroll
    for (int i = 0; i < 4; i++) {
        int c2 = c20 + ty * 4 + i;
        size_t base = (size_t)(n * Cc + c2) * Ss + s0 + tx * 4;
        float4 xr = *(const float4*)&x[base];
        float bb = bo[c2];
        float4 ov = make_float4(acc[i][0] + bb + xr.x,
                                acc[i][1] + bb + xr.y,
                                acc[i][2] + bb + xr.z,
                                acc[i][3] + bb + xr.w);
        *(float4*)&out[base] = ov;
    }
}

// ---------------------------------------------------------------------------
extern "C" void kernel_launch(void* const* d_in, const int* in_sizes, int n_in,
                              void* d_out, int out_size)
{
    const float* x    = (const float*)d_in[0];
    const float* gsc  = (const float*)d_in[1];
    const float* gbi  = (const float*)d_in[2];
    const float* wqkv = (const float*)d_in[3];
    const float* bqkv = (const float*)d_in[4];
    const float* wout = (const float*)d_in[5];
    const float* bout = (const float*)d_in[6];
    float* out = (float*)d_out;

    gn_kernel<<<Nn * 32, 256>>>(x, gsc, gbi);
    qkv_kernel<<<dim3(Ss / 64, D3 / 64, Nn), 256>>>(wqkv, bqkv);

    const int attn_smem = 3 * 64 * 68 * 4;   // 52224 bytes > 48KB -> opt-in
    cudaFuncSetAttribute(attn_kernel, cudaFuncAttributeMaxDynamicSharedMemorySize, attn_smem);
    attn_kernel<<<dim3(Ss / 64, Nn * NHEADS), 256, attn_smem>>>();

    oproj_kernel<<<dim3(Ss / 64, Cc / 64, Nn), 256>>>(wout, bout, x, out);
}

// round 3
// speedup vs baseline: 3.1504x; 3.1504x over previous
#include <cuda_runtime.h>
#include <math.h>
#include <stdint.h>

// ---------------------------------------------------------------------------
// Problem constants
// ---------------------------------------------------------------------------
#define Nn 16            // B*T
#define Cc 512
#define Ss 1024          // H*W
#define NHEADS 8
#define HD 64
#define D3 1536          // 3*C

// ---------------------------------------------------------------------------
// Scratch (device globals; no cudaMalloc allowed)
// ---------------------------------------------------------------------------
__device__ float g_hn   [Nn * Ss * Cc];           // groupnorm out [n][s][c] (tf32)
__device__ float g_q    [Nn * NHEADS * Ss * HD];  // [nh][s][e] (tf32)
__device__ float g_k    [Nn * NHEADS * Ss * HD];  // [nh][s][e] (tf32)
__device__ float g_v    [Nn * NHEADS * HD * Ss];  // [nh][e][s] (tf32, transposed)
__device__ float g_att  [Nn * Ss * Cc];           // attn out [n][s][c] (tf32)
__device__ float g_wqkvT[D3 * Cc];                // w_qkv^T [d][c] (tf32)
__device__ float g_woutT[Cc * Cc];                // w_out^T [c2][c] (tf32)

// ---------------------------------------------------------------------------
// Helpers
// ---------------------------------------------------------------------------
__device__ __forceinline__ uint32_t smem_u32(const void* p) {
    uint32_t a;
    asm("{ .reg .u64 t; cvta.to.shared.u64 t, %1; cvt.u32.u64 %0, t; }"
        : "=r"(a) : "l"(p));
    return a;
}

__device__ __forceinline__ float tf32r(float x) {
    uint32_t u;
    asm("cvt.rna.tf32.f32 %0, %1;" : "=r"(u) : "f"(x));
    return __uint_as_float(u);
}

// m16n8k8 tf32 mma, D = A*B + D (in place)
__device__ __forceinline__ void mma8(float* d, const uint32_t* a, const uint32_t* b) {
    asm volatile(
        "mma.sync.aligned.m16n8k8.row.col.f32.tf32.tf32.f32 "
        "{%0,%1,%2,%3}, {%4,%5,%6,%7}, {%8,%9}, {%0,%1,%2,%3};"
        : "+f"(d[0]), "+f"(d[1]), "+f"(d[2]), "+f"(d[3])
        : "r"(a[0]), "r"(a[1]), "r"(a[2]), "r"(a[3]), "r"(b[0]), "r"(b[1]));
}

__device__ __forceinline__ void cp16(uint32_t dst, const void* src) {
    asm volatile("cp.async.cg.shared.global [%0], [%1], 16;" :: "r"(dst), "l"(src));
}
#define CP_COMMIT() asm volatile("cp.async.commit_group;" ::: "memory")
#define CP_WAIT0()  asm volatile("cp.async.wait_group 0;" ::: "memory")

// ---------------------------------------------------------------------------
// Kernel 0: weight transpose + tf32 rounding   in [512][Ccols] -> out [Ccols][512]
// ---------------------------------------------------------------------------
__global__ void __launch_bounds__(256) trans_kernel(const float* __restrict__ in,
                                                    int Ccols, int which)
{
    float* out = which ? g_woutT : g_wqkvT;
    __shared__ float t[32][33];
    int c0 = blockIdx.x * 32, r0 = blockIdx.y * 32;
    int tx = threadIdx.x, ty = threadIdx.y;
#pragma unroll
    for (int i = 0; i < 32; i += 8)
        t[ty + i][tx] = in[(size_t)(r0 + ty + i) * Ccols + c0 + tx];
    __syncthreads();
#pragma unroll
    for (int i = 0; i < 32; i += 8)
        out[(size_t)(c0 + ty + i) * 512 + r0 + tx] = tf32r(t[tx][ty + i]);
}

// ---------------------------------------------------------------------------
// Kernel 1: GroupNorm (32 groups, eps=1e-6) -> g_hn [n][s][c] (tf32)
// ---------------------------------------------------------------------------
__global__ void __launch_bounds__(256) gn_kernel(const float* __restrict__ x,
                                                 const float* __restrict__ sc,
                                                 const float* __restrict__ bi)
{
    extern __shared__ float smt[];   // [1024][17]
    int n = blockIdx.x >> 5;
    int g = blockIdx.x & 31;
    const float* px = x + (size_t)(n * Cc + g * 16) * Ss;
    float* ph = g_hn + (size_t)n * Ss * Cc + g * 16;
    int tid = threadIdx.x;
    const int M = 16 * Ss;   // 16384

    float s = 0.f, ss = 0.f;
    for (int i = tid * 4; i < M; i += 1024) {
        float4 v = *(const float4*)&px[i];
        s  += v.x + v.y + v.z + v.w;
        ss += v.x*v.x + v.y*v.y + v.z*v.z + v.w*v.w;
    }
#pragma unroll
    for (int o = 16; o; o >>= 1) {
        s  += __shfl_xor_sync(0xffffffffu, s,  o);
        ss += __shfl_xor_sync(0xffffffffu, ss, o);
    }
    __shared__ float r0[8], r1[8];
    __shared__ float s_mean, s_inv;
    if ((tid & 31) == 0) { r0[tid >> 5] = s; r1[tid >> 5] = ss; }
    __syncthreads();
    if (tid == 0) {
        float a = 0.f, b2 = 0.f;
#pragma unroll
        for (int i = 0; i < 8; i++) { a += r0[i]; b2 += r1[i]; }
        float mean = a / (float)M;
        float var  = b2 / (float)M - mean * mean;
        s_mean = mean;
        s_inv  = rsqrtf(var + 1e-6f);
    }
    __syncthreads();
    float mean = s_mean, inv = s_inv;

    for (int i = tid * 4; i < M; i += 1024) {
        int c  = i >> 10;
        int sp = i & 1023;
        float scv = sc[g * 16 + c] * inv;
        float biv = bi[g * 16 + c] - mean * scv;
        float4 v = *(const float4*)&px[i];
        smt[(sp + 0) * 17 + c] = tf32r(v.x * scv + biv);
        smt[(sp + 1) * 17 + c] = tf32r(v.y * scv + biv);
        smt[(sp + 2) * 17 + c] = tf32r(v.z * scv + biv);
        smt[(sp + 3) * 17 + c] = tf32r(v.w * scv + biv);
    }
    __syncthreads();

#pragma unroll
    for (int j = 0; j < 4; j++) {
        int sp = tid * 4 + j;
        const float* row = &smt[sp * 17];
        float* dst = ph + (size_t)sp * Cc;
#pragma unroll
        for (int q = 0; q < 4; q++) {
            float4 o = make_float4(row[q*4+0], row[q*4+1], row[q*4+2], row[q*4+3]);
            *(float4*)&dst[q * 4] = o;
        }
    }
}

// ---------------------------------------------------------------------------
// Kernel 2: tf32 mma.sync GEMM, block tile 128(M=s) x 128(N=d), K=512, BK=32.
// 256 threads = 8 warps as 4(M) x 2(N); warp tile 32x64.
// A[m][k] and B[n][k] SMEM tiles, stride 36 (=> bank = 4g+tg, conflict-free).
//   mode 0 (qkv):   A=g_hn, B=g_wqkvT; out -> g_q/g_k [nh][s][e], g_v [nh][e][s]
//   mode 1 (oproj): A=g_att, B=g_woutT; out[n][d][s] = D + bias + x
// ---------------------------------------------------------------------------
__global__ void __launch_bounds__(256, 2) gemm_mma(const float* __restrict__ bias,
                                                   const float* __restrict__ xres,
                                                   float* __restrict__ out,
                                                   int mode)
{
    extern __shared__ float sm[];
    uint32_t sbase = smem_u32(sm);
    int tid = threadIdx.x, lane = tid & 31, wid = tid >> 5;
    int g = lane >> 2, tg = lane & 3;
    int n = blockIdx.z, s0 = blockIdx.x * 128, d0 = blockIdx.y * 128;
    int wm = wid & 3, wn = wid >> 2;

    const float* Ag = (mode ? g_att : g_hn) + ((size_t)n * Ss + s0) * Cc;
    const float* Bg = (mode ? g_woutT : g_wqkvT) + (size_t)d0 * Cc;

    // smem float layout: A(b) at b*4608, B(b) at 9216 + b*4608   (128 rows x 36)
    float C[2][8][4] = {};

    // prologue: chunk 0 -> buf 0
#pragma unroll
    for (int i = 0; i < 4; i++) {
        int f = tid + i * 256;
        int row = f >> 3, c4 = f & 7;
        cp16(sbase + (uint32_t)((row * 36 + c4 * 4) * 4),
             Ag + (size_t)row * Cc + c4 * 4);
        cp16(sbase + (uint32_t)((9216 + row * 36 + c4 * 4) * 4),
             Bg + (size_t)row * Cc + c4 * 4);
    }
    CP_COMMIT();
    CP_WAIT0();
    __syncthreads();

    for (int kc = 0; kc < 16; kc++) {
        int b = kc & 1;
        if (kc < 15) {
            int nb = b ^ 1;
            int koff = (kc + 1) * 32;
#pragma unroll
            for (int i = 0; i < 4; i++) {
                int f = tid + i * 256;
                int row = f >> 3, c4 = f & 7;
                cp16(sbase + (uint32_t)((nb * 4608 + row * 36 + c4 * 4) * 4),
                     Ag + (size_t)row * Cc + koff + c4 * 4);
                cp16(sbase + (uint32_t)((9216 + nb * 4608 + row * 36 + c4 * 4) * 4),
                     Bg + (size_t)row * Cc + koff + c4 * 4);
            }
            CP_COMMIT();
        }
        const float* As = sm + b * 4608;
        const float* Bs = sm + 9216 + b * 4608;
#pragma unroll
        for (int ks = 0; ks < 4; ks++) {
            int k0 = ks * 8;
            uint32_t a[2][4], bb[8][2];
#pragma unroll
            for (int tm = 0; tm < 2; tm++) {
                int r = wm * 32 + tm * 16 + g;
                a[tm][0] = __float_as_uint(As[r * 36 + k0 + tg]);
                a[tm][1] = __float_as_uint(As[(r + 8) * 36 + k0 + tg]);
                a[tm][2] = __float_as_uint(As[r * 36 + k0 + tg + 4]);
                a[tm][3] = __float_as_uint(As[(r + 8) * 36 + k0 + tg + 4]);
            }
#pragma unroll
            for (int tn = 0; tn < 8; tn++) {
                int c = wn * 64 + tn * 8 + g;
                bb[tn][0] = __float_as_uint(Bs[c * 36 + k0 + tg]);
                bb[tn][1] = __float_as_uint(Bs[c * 36 + k0 + tg + 4]);
            }
#pragma unroll
            for (int tm = 0; tm < 2; tm++)
#pragma unroll
                for (int tn = 0; tn < 8; tn++)
                    mma8(C[tm][tn], a[tm], bb[tn]);
        }
        CP_WAIT0();
        __syncthreads();
    }

    // epilogue
#pragma unroll
    for (int tm = 0; tm < 2; tm++) {
#pragma unroll
        for (int hh = 0; hh < 2; hh++) {
            int m = s0 + wm * 32 + tm * 16 + g + hh * 8;
#pragma unroll
            for (int tn = 0; tn < 8; tn++) {
                int d = d0 + wn * 64 + tn * 8 + 2 * tg;
                float v0 = C[tm][tn][hh * 2 + 0] + __ldg(&bias[d]);
                float v1 = C[tm][tn][hh * 2 + 1] + __ldg(&bias[d + 1]);
                if (mode == 0) {
                    int head = d / 192, t = d % 192;
                    int part = t >> 6, e = t & 63;
                    size_t nh = (size_t)(n * 8 + head);
                    if (part == 0) {
                        float2 val = make_float2(tf32r(v0), tf32r(v1));
                        *(float2*)&g_q[(nh * Ss + m) * HD + e] = val;
                    } else if (part == 1) {
                        float2 val = make_float2(tf32r(v0), tf32r(v1));
                        *(float2*)&g_k[(nh * Ss + m) * HD + e] = val;
                    } else {
                        g_v[(nh * HD + e) * Ss + m]     = tf32r(v0);
                        g_v[(nh * HD + e + 1) * Ss + m] = tf32r(v1);
                    }
                } else {
                    size_t gi = ((size_t)n * Cc + d) * Ss + m;
                    out[gi]      = v0 + xres[gi];
                    out[gi + Ss] = v1 + xres[gi + Ss];
                }
            }
        }
    }
}

// ---------------------------------------------------------------------------
// Kernel 3: flash attention with tf32 mma.sync.
// 256 threads = 8 warps; block = (nh, 128 q rows); warp owns 16 q rows.
// Smem: Ks[64][68] (K tile [j][e]), Vs[64][68] (V^T tile [e][j]),
//       Qs[128][68], Ps per-warp [16][68].  All strides 68 => conflict-free frags.
// ---------------------------------------------------------------------------
#define ATT_SMEM 104448

__global__ void __launch_bounds__(256, 2) attn_mma()
{
    extern __shared__ float sm[];
    float* Ks = sm;                  // 64*68 = 4352
    float* Vs = sm + 4352;           // [e][j]
    float* Qs = sm + 8704;           // [128][68]
    float* Ps = sm + 17408;          // per warp [16][68] (1088 floats each)

    int tid = threadIdx.x, lane = tid & 31, w = tid >> 5;
    int g = lane >> 2, tg = lane & 3;
    int nh = blockIdx.y, q0 = blockIdx.x * 128;
    const float* Q = g_q + (size_t)nh * Ss * HD;
    const float* K = g_k + (size_t)nh * Ss * HD;
    const float* V = g_v + (size_t)nh * HD * Ss;

    // load Q tile, scaled by 1/8 (exact power of two preserves tf32)
#pragma unroll
    for (int i = 0; i < 8; i++) {
        int f = tid + i * 256;
        int row = f >> 4, c4 = f & 15;
        float4 v = *(const float4*)&Q[(size_t)(q0 + row) * HD + c4 * 4];
        v.x *= 0.125f; v.y *= 0.125f; v.z *= 0.125f; v.w *= 0.125f;
        *(float4*)&Qs[row * 68 + c4 * 4] = v;
    }

    float O[8][4] = {};
    float m0 = -1e30f, m1 = -1e30f, l0 = 0.f, l1 = 0.f;
    float* Pw = Ps + w * 1088;
    int qb = w * 16;

    for (int kt = 0; kt < 16; kt++) {
        __syncthreads();
#pragma unroll
        for (int i = 0; i < 4; i++) {
            int f = tid + i * 256;
            int r = f >> 4, c4 = f & 15;
            *(float4*)&Ks[r * 68 + c4 * 4] =
                *(const float4*)&K[(size_t)(kt * 64 + r) * HD + c4 * 4];
            *(float4*)&Vs[r * 68 + c4 * 4] =
                *(const float4*)&V[(size_t)r * Ss + kt * 64 + c4 * 4];
        }
        __syncthreads();

        // S = Q @ K^T  (warp: 16 q rows x 64 keys)
        float S[8][4] = {};
#pragma unroll
        for (int ks = 0; ks < 8; ks++) {
            int k0 = ks * 8;
            uint32_t a[4];
            a[0] = __float_as_uint(Qs[(qb + g) * 68 + k0 + tg]);
            a[1] = __float_as_uint(Qs[(qb + g + 8) * 68 + k0 + tg]);
            a[2] = __float_as_uint(Qs[(qb + g) * 68 + k0 + tg + 4]);
            a[3] = __float_as_uint(Qs[(qb + g + 8) * 68 + k0 + tg + 4]);
#pragma unroll
            for (int tn = 0; tn < 8; tn++) {
                uint32_t b[2];
                b[0] = __float_as_uint(Ks[(tn * 8 + g) * 68 + k0 + tg]);
                b[1] = __float_as_uint(Ks[(tn * 8 + g) * 68 + k0 + tg + 4]);
                mma8(S[tn], a, b);
            }
        }

        // online softmax; rows g (regs 0,1) and g+8 (regs 2,3)
        float mx0 = -1e30f, mx1 = -1e30f;
#pragma unroll
        for (int tn = 0; tn < 8; tn++) {
            mx0 = fmaxf(mx0, fmaxf(S[tn][0], S[tn][1]));
            mx1 = fmaxf(mx1, fmaxf(S[tn][2], S[tn][3]));
        }
        mx0 = fmaxf(mx0, __shfl_xor_sync(0xffffffffu, mx0, 1));
        mx0 = fmaxf(mx0, __shfl_xor_sync(0xffffffffu, mx0, 2));
        mx1 = fmaxf(mx1, __shfl_xor_sync(0xffffffffu, mx1, 1));
        mx1 = fmaxf(mx1, __shfl_xor_sync(0xffffffffu, mx1, 2));
        float mn0 = fmaxf(m0, mx0), mn1 = fmaxf(m1, mx1);
        float cr0 = __expf(m0 - mn0), cr1 = __expf(m1 - mn1);
        float rs0 = 0.f, rs1 = 0.f;
#pragma unroll
        for (int tn = 0; tn < 8; tn++) {
            S[tn][0] = __expf(S[tn][0] - mn0);
            S[tn][1] = __expf(S[tn][1] - mn0);
            S[tn][2] = __expf(S[tn][2] - mn1);
            S[tn][3] = __expf(S[tn][3] - mn1);
            rs0 += S[tn][0] + S[tn][1];
            rs1 += S[tn][2] + S[tn][3];
        }
        rs0 += __shfl_xor_sync(0xffffffffu, rs0, 1);
        rs0 += __shfl_xor_sync(0xffffffffu, rs0, 2);
        rs1 += __shfl_xor_sync(0xffffffffu, rs1, 1);
        rs1 += __shfl_xor_sync(0xffffffffu, rs1, 2);
        l0 = l0 * cr0 + rs0;  l1 = l1 * cr1 + rs1;
        m0 = mn0;  m1 = mn1;

#pragma unroll
        for (int tn = 0; tn < 8; tn++) {
            O[tn][0] *= cr0; O[tn][1] *= cr0;
            O[tn][2] *= cr1; O[tn][3] *= cr1;
            float2 p0 = make_float2(tf32r(S[tn][0]), tf32r(S[tn][1]));
            float2 p1 = make_float2(tf32r(S[tn][2]), tf32r(S[tn][3]));
            *(float2*)&Pw[g * 68 + tn * 8 + 2 * tg] = p0;
            *(float2*)&Pw[(g + 8) * 68 + tn * 8 + 2 * tg] = p1;
        }
        __syncwarp();

        // O += P @ V
#pragma unroll
        for (int ks = 0; ks < 8; ks++) {
            int k0 = ks * 8;
            uint32_t a[4];
            a[0] = __float_as_uint(Pw[g * 68 + k0 + tg]);
            a[1] = __float_as_uint(Pw[(g + 8) * 68 + k0 + tg]);
            a[2] = __float_as_uint(Pw[g * 68 + k0 + tg + 4]);
            a[3] = __float_as_uint(Pw[(g + 8) * 68 + k0 + tg + 4]);
#pragma unroll
            for (int tn = 0; tn < 8; tn++) {
                uint32_t b[2];
                b[0] = __float_as_uint(Vs[(tn * 8 + g) * 68 + k0 + tg]);
                b[1] = __float_as_uint(Vs[(tn * 8 + g) * 68 + k0 + tg + 4]);
                mma8(O[tn], a, b);
            }
        }
        __syncwarp();
    }

    // epilogue -> g_att[n][s][head*64 + e], tf32-rounded
    int n = nh >> 3, head = nh & 7;
    float inv0 = 1.f / l0, inv1 = 1.f / l1;
    int srow0 = q0 + qb + g, srow1 = srow0 + 8;
    float* dst = g_att + (size_t)n * Ss * Cc + head * 64;
#pragma unroll
    for (int tn = 0; tn < 8; tn++) {
        int c = tn * 8 + 2 * tg;
        float2 v0 = make_float2(tf32r(O[tn][0] * inv0), tf32r(O[tn][1] * inv0));
        float2 v1 = make_float2(tf32r(O[tn][2] * inv1), tf32r(O[tn][3] * inv1));
        *(float2*)&dst[(size_t)srow0 * Cc + c] = v0;
        *(float2*)&dst[(size_t)srow1 * Cc + c] = v1;
    }
}

// ---------------------------------------------------------------------------
extern "C" void kernel_launch(void* const* d_in, const int* in_sizes, int n_in,
                              void* d_out, int out_size)
{
    const float* x    = (const float*)d_in[0];
    const float* gsc  = (const float*)d_in[1];
    const float* gbi  = (const float*)d_in[2];
    const float* wqkv = (const float*)d_in[3];
    const float* bqkv = (const float*)d_in[4];
    const float* wout = (const float*)d_in[5];
    const float* bout = (const float*)d_in[6];
    float* out = (float*)d_out;

    // weight transposes (+tf32 rounding)
    trans_kernel<<<dim3(D3 / 32, Cc / 32), dim3(32, 8)>>>(wqkv, D3, 0);
    trans_kernel<<<dim3(Cc / 32, Cc / 32), dim3(32, 8)>>>(wout, Cc, 1);

    // groupnorm (transposed tf32 output)
    cudaFuncSetAttribute(gn_kernel, cudaFuncAttributeMaxDynamicSharedMemorySize, 69632);
    gn_kernel<<<Nn * 32, 256, 69632>>>(x, gsc, gbi);

    // qkv projection (tf32 mma.sync)
    const int gemm_smem = 18432 * 4;  // 73728
    cudaFuncSetAttribute(gemm_mma, cudaFuncAttributeMaxDynamicSharedMemorySize, gemm_smem);
    gemm_mma<<<dim3(Ss / 128, D3 / 128, Nn), 256, gemm_smem>>>(bqkv, nullptr, nullptr, 0);

    // attention (tf32 mma.sync flash)
    cudaFuncSetAttribute(attn_mma, cudaFuncAttributeMaxDynamicSharedMemorySize, ATT_SMEM);
    attn_mma<<<dim3(Ss / 128, Nn * NHEADS), 256, ATT_SMEM>>>();

    // output projection + residual (tf32 mma.sync)
    gemm_mma<<<dim3(Ss / 128, Cc / 128, Nn), 256, gemm_smem>>>(bout, x, out, 1);
}

// round 4
// speedup vs baseline: 3.3719x; 1.0703x over previous
#include <cuda_runtime.h>
#include <math.h>
#include <stdint.h>

// ---------------------------------------------------------------------------
// Problem constants
// ---------------------------------------------------------------------------
#define Nn 16            // B*T
#define Cc 512
#define Ss 1024          // H*W
#define NHEADS 8
#define HD 64
#define D3 1536          // 3*C

// ---------------------------------------------------------------------------
// Scratch (device globals; no cudaMalloc allowed)
// ---------------------------------------------------------------------------
__device__ float g_hn   [Nn * Ss * Cc];           // groupnorm out [n][s][c] (tf32)
__device__ float g_q    [Nn * NHEADS * Ss * HD];  // [nh][s][e] (tf32)
__device__ float g_k    [Nn * NHEADS * Ss * HD];  // [nh][s][e] (tf32)
__device__ float g_v    [Nn * NHEADS * HD * Ss];  // [nh][e][s] (tf32, transposed)
__device__ float g_att  [Nn * Ss * Cc];           // attn out [n][s][c] (tf32)
__device__ float g_wqkvT[D3 * Cc];                // w_qkv^T [d][c] (tf32)
__device__ float g_woutT[Cc * Cc];                // w_out^T [c2][c] (tf32)

// ---------------------------------------------------------------------------
// Helpers
// ---------------------------------------------------------------------------
__device__ __forceinline__ uint32_t smem_u32(const void* p) {
    uint32_t a;
    asm("{ .reg .u64 t; cvta.to.shared.u64 t, %1; cvt.u32.u64 %0, t; }"
        : "=r"(a) : "l"(p));
    return a;
}

__device__ __forceinline__ float tf32r(float x) {
    uint32_t u;
    asm("cvt.rna.tf32.f32 %0, %1;" : "=r"(u) : "f"(x));
    return __uint_as_float(u);
}

// m16n8k8 tf32 mma, D = A*B + D (in place)
__device__ __forceinline__ void mma8(float* d, const uint32_t* a, const uint32_t* b) {
    asm volatile(
        "mma.sync.aligned.m16n8k8.row.col.f32.tf32.tf32.f32 "
        "{%0,%1,%2,%3}, {%4,%5,%6,%7}, {%8,%9}, {%0,%1,%2,%3};"
        : "+f"(d[0]), "+f"(d[1]), "+f"(d[2]), "+f"(d[3])
        : "r"(a[0]), "r"(a[1]), "r"(a[2]), "r"(a[3]), "r"(b[0]), "r"(b[1]));
}

__device__ __forceinline__ void cp16(uint32_t dst, const void* src) {
    asm volatile("cp.async.cg.shared.global [%0], [%1], 16;" :: "r"(dst), "l"(src));
}
#define CP_COMMIT() asm volatile("cp.async.commit_group;" ::: "memory")
#define CP_WAIT1()  asm volatile("cp.async.wait_group 1;" ::: "memory")

// ---------------------------------------------------------------------------
// Kernel 0: weight transpose + tf32 rounding   in [512][Ccols] -> out [Ccols][512]
// ---------------------------------------------------------------------------
__global__ void __launch_bounds__(256) trans_kernel(const float* __restrict__ in,
                                                    int Ccols, int which)
{
    float* out = which ? g_woutT : g_wqkvT;
    __shared__ float t[32][33];
    int c0 = blockIdx.x * 32, r0 = blockIdx.y * 32;
    int tx = threadIdx.x, ty = threadIdx.y;
#pragma unroll
    for (int i = 0; i < 32; i += 8)
        t[ty + i][tx] = in[(size_t)(r0 + ty + i) * Ccols + c0 + tx];
    __syncthreads();
#pragma unroll
    for (int i = 0; i < 32; i += 8)
        out[(size_t)(c0 + ty + i) * 512 + r0 + tx] = tf32r(t[tx][ty + i]);
}

// ---------------------------------------------------------------------------
// Kernel 1: GroupNorm (32 groups, eps=1e-6) -> g_hn [n][s][c] (tf32)
// ---------------------------------------------------------------------------
__global__ void __launch_bounds__(256) gn_kernel(const float* __restrict__ x,
                                                 const float* __restrict__ sc,
                                                 const float* __restrict__ bi)
{
    extern __shared__ float smt[];   // [1024][17]
    int n = blockIdx.x >> 5;
    int g = blockIdx.x & 31;
    const float* px = x + (size_t)(n * Cc + g * 16) * Ss;
    float* ph = g_hn + (size_t)n * Ss * Cc + g * 16;
    int tid = threadIdx.x;
    const int M = 16 * Ss;   // 16384

    float s = 0.f, ss = 0.f;
    for (int i = tid * 4; i < M; i += 1024) {
        float4 v = *(const float4*)&px[i];
        s  += v.x + v.y + v.z + v.w;
        ss += v.x*v.x + v.y*v.y + v.z*v.z + v.w*v.w;
    }
#pragma unroll
    for (int o = 16; o; o >>= 1) {
        s  += __shfl_xor_sync(0xffffffffu, s,  o);
        ss += __shfl_xor_sync(0xffffffffu, ss, o);
    }
    __shared__ float r0[8], r1[8];
    __shared__ float s_mean, s_inv;
    if ((tid & 31) == 0) { r0[tid >> 5] = s; r1[tid >> 5] = ss; }
    __syncthreads();
    if (tid == 0) {
        float a = 0.f, b2 = 0.f;
#pragma unroll
        for (int i = 0; i < 8; i++) { a += r0[i]; b2 += r1[i]; }
        float mean = a / (float)M;
        float var  = b2 / (float)M - mean * mean;
        s_mean = mean;
        s_inv  = rsqrtf(var + 1e-6f);
    }
    __syncthreads();
    float mean = s_mean, inv = s_inv;

    for (int i = tid * 4; i < M; i += 1024) {
        int c  = i >> 10;
        int sp = i & 1023;
        float scv = sc[g * 16 + c] * inv;
        float biv = bi[g * 16 + c] - mean * scv;
        float4 v = *(const float4*)&px[i];
        smt[(sp + 0) * 17 + c] = tf32r(v.x * scv + biv);
        smt[(sp + 1) * 17 + c] = tf32r(v.y * scv + biv);
        smt[(sp + 2) * 17 + c] = tf32r(v.z * scv + biv);
        smt[(sp + 3) * 17 + c] = tf32r(v.w * scv + biv);
    }
    __syncthreads();

#pragma unroll
    for (int j = 0; j < 4; j++) {
        int sp = tid * 4 + j;
        const float* row = &smt[sp * 17];
        float* dst = ph + (size_t)sp * Cc;
#pragma unroll
        for (int q = 0; q < 4; q++) {
            float4 o = make_float4(row[q*4+0], row[q*4+1], row[q*4+2], row[q*4+3]);
            *(float4*)&dst[q * 4] = o;
        }
    }
}

// ---------------------------------------------------------------------------
// Kernel 2: tf32 mma.sync GEMM, tile 128(M=s) x 128(N=d), K=512, BK=32.
// 3-stage cp.async pipeline (wait_group 1). 8 warps = 4(M) x 2(N), warp 32x64.
// SMEM stride 36 floats => conflict-free fragment loads.
// ---------------------------------------------------------------------------
__device__ __forceinline__ void gemm_load(uint32_t sbase, int soff,
                                          const float* __restrict__ Ag,
                                          const float* __restrict__ Bg,
                                          int koff, int tid)
{
#pragma unroll
    for (int i = 0; i < 4; i++) {
        int f = tid + i * 256;
        int row = f >> 3, c4 = f & 7;
        cp16(sbase + (uint32_t)((soff + row * 36 + c4 * 4) * 4),
             Ag + (size_t)row * Cc + koff + c4 * 4);
        cp16(sbase + (uint32_t)((soff + 4608 + row * 36 + c4 * 4) * 4),
             Bg + (size_t)row * Cc + koff + c4 * 4);
    }
}

__global__ void __launch_bounds__(256, 2) gemm_mma(const float* __restrict__ bias,
                                                   const float* __restrict__ xres,
                                                   float* __restrict__ out,
                                                   int mode)
{
    extern __shared__ float sm[];
    uint32_t sbase = smem_u32(sm);
    int tid = threadIdx.x, lane = tid & 31, wid = tid >> 5;
    int g = lane >> 2, tg = lane & 3;
    int n = blockIdx.z, s0 = blockIdx.x * 128, d0 = blockIdx.y * 128;
    int wm = wid & 3, wn = wid >> 2;

    const float* Ag = (mode ? g_att : g_hn) + ((size_t)n * Ss + s0) * Cc;
    const float* Bg = (mode ? g_woutT : g_wqkvT) + (size_t)d0 * Cc;

    float C[2][8][4] = {};

    // prologue: stages 0,1
    gemm_load(sbase, 0, Ag, Bg, 0, tid);
    CP_COMMIT();
    gemm_load(sbase, 9216, Ag, Bg, 32, tid);
    CP_COMMIT();

    for (int kc = 0; kc < 16; kc++) {
        CP_WAIT1();
        __syncthreads();
        int b = kc % 3;
        // prefetch kc+2 into stage (kc+2)%3 (freed: all warps are past MMA(kc-1))
        if (kc + 2 < 16)
            gemm_load(sbase, ((kc + 2) % 3) * 9216, Ag, Bg, (kc + 2) * 32, tid);
        CP_COMMIT();

        const float* As = sm + b * 9216;
        const float* Bs = sm + b * 9216 + 4608;
#pragma unroll
        for (int ks = 0; ks < 4; ks++) {
            int k0 = ks * 8;
            uint32_t a[2][4], bb[8][2];
#pragma unroll
            for (int tm = 0; tm < 2; tm++) {
                int r = wm * 32 + tm * 16 + g;
                a[tm][0] = __float_as_uint(As[r * 36 + k0 + tg]);
                a[tm][1] = __float_as_uint(As[(r + 8) * 36 + k0 + tg]);
                a[tm][2] = __float_as_uint(As[r * 36 + k0 + tg + 4]);
                a[tm][3] = __float_as_uint(As[(r + 8) * 36 + k0 + tg + 4]);
            }
#pragma unroll
            for (int tn = 0; tn < 8; tn++) {
                int c = wn * 64 + tn * 8 + g;
                bb[tn][0] = __float_as_uint(Bs[c * 36 + k0 + tg]);
                bb[tn][1] = __float_as_uint(Bs[c * 36 + k0 + tg + 4]);
            }
#pragma unroll
            for (int tm = 0; tm < 2; tm++)
#pragma unroll
                for (int tn = 0; tn < 8; tn++)
                    mma8(C[tm][tn], a[tm], bb[tn]);
        }
    }

    // epilogue
#pragma unroll
    for (int tm = 0; tm < 2; tm++) {
#pragma unroll
        for (int hh = 0; hh < 2; hh++) {
            int m = s0 + wm * 32 + tm * 16 + g + hh * 8;
#pragma unroll
            for (int tn = 0; tn < 8; tn++) {
                int d = d0 + wn * 64 + tn * 8 + 2 * tg;
                float v0 = C[tm][tn][hh * 2 + 0] + __ldg(&bias[d]);
                float v1 = C[tm][tn][hh * 2 + 1] + __ldg(&bias[d + 1]);
                if (mode == 0) {
                    int head = d / 192, t = d % 192;
                    int part = t >> 6, e = t & 63;
                    size_t nh = (size_t)(n * 8 + head);
                    if (part == 0) {
                        float2 val = make_float2(tf32r(v0), tf32r(v1));
                        *(float2*)&g_q[(nh * Ss + m) * HD + e] = val;
                    } else if (part == 1) {
                        float2 val = make_float2(tf32r(v0), tf32r(v1));
                        *(float2*)&g_k[(nh * Ss + m) * HD + e] = val;
                    } else {
                        g_v[(nh * HD + e) * Ss + m]     = tf32r(v0);
                        g_v[(nh * HD + e + 1) * Ss + m] = tf32r(v1);
                    }
                } else {
                    size_t gi = ((size_t)n * Cc + d) * Ss + m;
                    out[gi]      = v0 + xres[gi];
                    out[gi + Ss] = v1 + xres[gi + Ss];
                }
            }
        }
    }
}

// ---------------------------------------------------------------------------
// Kernel 3: flash attention, tf32 mma.sync, double-buffered cp.async K/V,
// register shuffle-transpose for P (no smem round trip).
// SMEM floats: KV stage b: K at b*8704, V at b*8704+4352; Q at 17408.
// Total = 26112 floats = 104448 B. 256 threads, 2 CTAs/SM.
// ---------------------------------------------------------------------------
#define ATT_SMEM 104448

__device__ __forceinline__ void attn_load_kv(uint32_t sbase, int b,
                                             const float* __restrict__ K,
                                             const float* __restrict__ V,
                                             int kt, int tid)
{
#pragma unroll
    for (int i = 0; i < 4; i++) {
        int f = tid + i * 256;
        int r = f >> 4, c4 = f & 15;
        cp16(sbase + (uint32_t)((b * 8704 + r * 68 + c4 * 4) * 4),
             K + (size_t)(kt * 64 + r) * HD + c4 * 4);
        cp16(sbase + (uint32_t)((b * 8704 + 4352 + r * 68 + c4 * 4) * 4),
             V + (size_t)r * Ss + kt * 64 + c4 * 4);
    }
}

__global__ void __launch_bounds__(256, 2) attn_mma()
{
    extern __shared__ float sm[];
    uint32_t sbase = smem_u32(sm);
    float* Qs = sm + 17408;

    int tid = threadIdx.x, lane = tid & 31, w = tid >> 5;
    int g = lane >> 2, tg = lane & 3;
    int nh = blockIdx.y, q0 = blockIdx.x * 128;
    const float* Q = g_q + (size_t)nh * Ss * HD;
    const float* K = g_k + (size_t)nh * Ss * HD;
    const float* V = g_v + (size_t)nh * HD * Ss;

    // prologue: Q + KV(0) -> group 0; KV(1) -> group 1
#pragma unroll
    for (int i = 0; i < 8; i++) {
        int f = tid + i * 256;
        int row = f >> 4, c4 = f & 15;
        cp16(sbase + (uint32_t)((17408 + row * 68 + c4 * 4) * 4),
             Q + (size_t)(q0 + row) * HD + c4 * 4);
    }
    attn_load_kv(sbase, 0, K, V, 0, tid);
    CP_COMMIT();
    attn_load_kv(sbase, 1, K, V, 1, tid);
    CP_COMMIT();

    float O[8][4] = {};
    float m0 = -1e30f, m1 = -1e30f, l0 = 0.f, l1 = 0.f;
    int qb = w * 16;
    int srcA = g * 4 + (tg >> 1);      // shuffle source lanes for P transpose
    int srcB = srcA + 2;
    bool oddc = (tg & 1);

    for (int kt = 0; kt < 16; kt++) {
        CP_WAIT1();
        __syncthreads();
        int b = kt & 1;
        const float* Ks = sm + b * 8704;
        const float* Vs = sm + b * 8704 + 4352;

        // S = Q @ K^T  (warp: 16 q rows x 64 keys)
        float S[8][4] = {};
#pragma unroll
        for (int ks = 0; ks < 8; ks++) {
            int k0 = ks * 8;
            uint32_t a[4];
            a[0] = __float_as_uint(Qs[(qb + g) * 68 + k0 + tg]);
            a[1] = __float_as_uint(Qs[(qb + g + 8) * 68 + k0 + tg]);
            a[2] = __float_as_uint(Qs[(qb + g) * 68 + k0 + tg + 4]);
            a[3] = __float_as_uint(Qs[(qb + g + 8) * 68 + k0 + tg + 4]);
#pragma unroll
            for (int tn = 0; tn < 8; tn++) {
                uint32_t bfr[2];
                bfr[0] = __float_as_uint(Ks[(tn * 8 + g) * 68 + k0 + tg]);
                bfr[1] = __float_as_uint(Ks[(tn * 8 + g) * 68 + k0 + tg + 4]);
                mma8(S[tn], a, bfr);
            }
        }

        // scale by 1/sqrt(64) and online softmax
        float mx0 = -1e30f, mx1 = -1e30f;
#pragma unroll
        for (int tn = 0; tn < 8; tn++) {
            S[tn][0] *= 0.125f; S[tn][1] *= 0.125f;
            S[tn][2] *= 0.125f; S[tn][3] *= 0.125f;
            mx0 = fmaxf(mx0, fmaxf(S[tn][0], S[tn][1]));
            mx1 = fmaxf(mx1, fmaxf(S[tn][2], S[tn][3]));
        }
        mx0 = fmaxf(mx0, __shfl_xor_sync(0xffffffffu, mx0, 1));
        mx0 = fmaxf(mx0, __shfl_xor_sync(0xffffffffu, mx0, 2));
        mx1 = fmaxf(mx1, __shfl_xor_sync(0xffffffffu, mx1, 1));
        mx1 = fmaxf(mx1, __shfl_xor_sync(0xffffffffu, mx1, 2));
        float mn0 = fmaxf(m0, mx0), mn1 = fmaxf(m1, mx1);
        float cr0 = __expf(m0 - mn0), cr1 = __expf(m1 - mn1);
        float rs0 = 0.f, rs1 = 0.f;
#pragma unroll
        for (int tn = 0; tn < 8; tn++) {
            S[tn][0] = tf32r(__expf(S[tn][0] - mn0));
            S[tn][1] = tf32r(__expf(S[tn][1] - mn0));
            S[tn][2] = tf32r(__expf(S[tn][2] - mn1));
            S[tn][3] = tf32r(__expf(S[tn][3] - mn1));
            rs0 += S[tn][0] + S[tn][1];
            rs1 += S[tn][2] + S[tn][3];
        }
        rs0 += __shfl_xor_sync(0xffffffffu, rs0, 1);
        rs0 += __shfl_xor_sync(0xffffffffu, rs0, 2);
        rs1 += __shfl_xor_sync(0xffffffffu, rs1, 1);
        rs1 += __shfl_xor_sync(0xffffffffu, rs1, 2);
        l0 = l0 * cr0 + rs0;  l1 = l1 * cr1 + rs1;
        m0 = mn0;  m1 = mn1;

#pragma unroll
        for (int tn = 0; tn < 8; tn++) {
            O[tn][0] *= cr0; O[tn][1] *= cr0;
            O[tn][2] *= cr1; O[tn][3] *= cr1;
        }

        // O += P @ V : rebuild P a-fragments from S c-fragments via quad shuffles.
        // a-frag (ks): rows {g, g+8}, cols {tg, tg+4} of P[16][64] k-group ks.
        // col c of row-quad is elem (c&1) of lane g*4 + (c>>1).
#pragma unroll
        for (int ks = 0; ks < 8; ks++) {
            float e00 = __shfl_sync(0xffffffffu, S[ks][0], srcA);
            float e01 = __shfl_sync(0xffffffffu, S[ks][1], srcA);
            float e10 = __shfl_sync(0xffffffffu, S[ks][2], srcA);
            float e11 = __shfl_sync(0xffffffffu, S[ks][3], srcA);
            float f00 = __shfl_sync(0xffffffffu, S[ks][0], srcB);
            float f01 = __shfl_sync(0xffffffffu, S[ks][1], srcB);
            float f10 = __shfl_sync(0xffffffffu, S[ks][2], srcB);
            float f11 = __shfl_sync(0xffffffffu, S[ks][3], srcB);
            uint32_t a[4];
            a[0] = __float_as_uint(oddc ? e01 : e00);
            a[1] = __float_as_uint(oddc ? e11 : e10);
            a[2] = __float_as_uint(oddc ? f01 : f00);
            a[3] = __float_as_uint(oddc ? f11 : f10);
            int k0 = ks * 8;
#pragma unroll
            for (int tn = 0; tn < 8; tn++) {
                uint32_t bfr[2];
                bfr[0] = __float_as_uint(Vs[(tn * 8 + g) * 68 + k0 + tg]);
                bfr[1] = __float_as_uint(Vs[(tn * 8 + g) * 68 + k0 + tg + 4]);
                mma8(O[tn], a, bfr);
            }
        }

        __syncthreads();   // all warps done reading buffer b
        if (kt + 2 < 16)
            attn_load_kv(sbase, b, K, V, kt + 2, tid);
        CP_COMMIT();
    }

    // epilogue -> g_att[n][s][head*64 + e], tf32-rounded
    int n = nh >> 3, head = nh & 7;
    float inv0 = 1.f / l0, inv1 = 1.f / l1;
    int srow0 = q0 + qb + g, srow1 = srow0 + 8;
    float* dst = g_att + (size_t)n * Ss * Cc + head * 64;
#pragma unroll
    for (int tn = 0; tn < 8; tn++) {
        int c = tn * 8 + 2 * tg;
        float2 v0 = make_float2(tf32r(O[tn][0] * inv0), tf32r(O[tn][1] * inv0));
        float2 v1 = make_float2(tf32r(O[tn][2] * inv1), tf32r(O[tn][3] * inv1));
        *(float2*)&dst[(size_t)srow0 * Cc + c] = v0;
        *(float2*)&dst[(size_t)srow1 * Cc + c] = v1;
    }
}

// ---------------------------------------------------------------------------
extern "C" void kernel_launch(void* const* d_in, const int* in_sizes, int n_in,
                              void* d_out, int out_size)
{
    const float* x    = (const float*)d_in[0];
    const float* gsc  = (const float*)d_in[1];
    const float* gbi  = (const float*)d_in[2];
    const float* wqkv = (const float*)d_in[3];
    const float* bqkv = (const float*)d_in[4];
    const float* wout = (const float*)d_in[5];
    const float* bout = (const float*)d_in[6];
    float* out = (float*)d_out;

    trans_kernel<<<dim3(D3 / 32, Cc / 32), dim3(32, 8)>>>(wqkv, D3, 0);
    trans_kernel<<<dim3(Cc / 32, Cc / 32), dim3(32, 8)>>>(wout, Cc, 1);

    cudaFuncSetAttribute(gn_kernel, cudaFuncAttributeMaxDynamicSharedMemorySize, 69632);
    gn_kernel<<<Nn * 32, 256, 69632>>>(x, gsc, gbi);

    const int gemm_smem = 27648 * 4;   // 3 stages x 9216 floats = 110592 B
    cudaFuncSetAttribute(gemm_mma, cudaFuncAttributeMaxDynamicSharedMemorySize, gemm_smem);
    gemm_mma<<<dim3(Ss / 128, D3 / 128, Nn), 256, gemm_smem>>>(bqkv, nullptr, nullptr, 0);

    cudaFuncSetAttribute(attn_mma, cudaFuncAttributeMaxDynamicSharedMemorySize, ATT_SMEM);
    attn_mma<<<dim3(Ss / 128, Nn * NHEADS), 256, ATT_SMEM>>>();

    gemm_mma<<<dim3(Ss / 128, Cc / 128, Nn), 256, gemm_smem>>>(bout, x, out, 1);
}